// round 10
// baseline (speedup 1.0000x reference)
#include <cuda_runtime.h>

#define NN 1024
#define HH 128
#define NJB 8           // j-blocks of 128

// Device-global scratch (no allocation allowed)
__device__ float g_part[NJB * NN * HH];   // per-jblock partial aggregates
__device__ float g_gi[NN * 3 * HH];       // gi = agg @ w_ih^T   [1024][384]
__device__ float g_gh[NN * 3 * HH];       // gh = nf  @ w_hh^T   [1024][384]

// ---------------------------------------------------------------------------
// Kernel A: fused [agg  ||  gh-GEMM].
// blocks [0,1024): barrier-free partial aggregation (round-9 code, at its
//   measured DRAM floor ~4.6 TB/s for this gated-scatter pattern).
// blocks [1024,1216): gh = nf @ w_hh^T, 32x64 tile, 2x4 microtile (low regs).
//   Runs concurrently with agg; agg's FMA pipe is 93% idle so this is free.
// __launch_bounds__(256,6) caps regs at ~42 so the gemm branch cannot
// destroy agg's occupancy.
// ---------------------------------------------------------------------------
__global__ __launch_bounds__(256, 6) void fused_agg_gh_kernel(
    const float* __restrict__ nf,
    const int*   __restrict__ adj,
    const float* __restrict__ T,
    const float* __restrict__ whh)
{
    __shared__ float4 sA[32][9];   // gemm branch only (14 KB total)
    __shared__ float4 sB[64][9];

    const int bx  = blockIdx.x;
    const int tid = threadIdx.x;

    if (bx < 1024) {
        // ---------------- aggregation (unchanged round 9) ----------------
        const int ib   = bx & 127;
        const int jb   = bx >> 7;
        const int lane = tid & 31;
        const int w    = tid >> 5;
        const int i    = ib * 8 + w;

        const float4* nf4 = (const float4*)nf;
        const float4* T4  = (const float4*)T;

        float4 a0 = make_float4(0.f,0.f,0.f,0.f);
        float4 a1 = make_float4(0.f,0.f,0.f,0.f);
        float4 a2 = make_float4(0.f,0.f,0.f,0.f);
        float4 a3 = make_float4(0.f,0.f,0.f,0.f);

        const int* adjrow = adj + (size_t)i * NN + jb * 128;

        #pragma unroll 1
        for (int c = 0; c < 4; c++) {
            const int av = __ldg(&adjrow[c * 32 + lane]);
            unsigned m = __ballot_sync(0xffffffffu, av != 0);
            int tot = __popc(m);

            const int    jbase   = jb * 128 + c * 32;
            const size_t rowbase = (size_t)i * NN + jbase;

            while (tot >= 4) {
                const int j0 = __ffs(m) - 1; m &= m - 1;
                const int j1 = __ffs(m) - 1; m &= m - 1;
                const int j2 = __ffs(m) - 1; m &= m - 1;
                const int j3 = __ffs(m) - 1; m &= m - 1;
                tot -= 4;
                float4 t0 = __ldcs(&T4[(rowbase + j0) * 32 + lane]);
                float4 t1 = __ldcs(&T4[(rowbase + j1) * 32 + lane]);
                float4 t2 = __ldcs(&T4[(rowbase + j2) * 32 + lane]);
                float4 t3 = __ldcs(&T4[(rowbase + j3) * 32 + lane]);
                float4 f0 = __ldg(&nf4[(size_t)(jbase + j0) * 32 + lane]);
                float4 f1 = __ldg(&nf4[(size_t)(jbase + j1) * 32 + lane]);
                float4 f2 = __ldg(&nf4[(size_t)(jbase + j2) * 32 + lane]);
                float4 f3 = __ldg(&nf4[(size_t)(jbase + j3) * 32 + lane]);
                a0.x += f0.x*t0.x; a0.y += f0.y*t0.y; a0.z += f0.z*t0.z; a0.w += f0.w*t0.w;
                a1.x += f1.x*t1.x; a1.y += f1.y*t1.y; a1.z += f1.z*t1.z; a1.w += f1.w*t1.w;
                a2.x += f2.x*t2.x; a2.y += f2.y*t2.y; a2.z += f2.z*t2.z; a2.w += f2.w*t2.w;
                a3.x += f3.x*t3.x; a3.y += f3.y*t3.y; a3.z += f3.z*t3.z; a3.w += f3.w*t3.w;
            }
            while (tot > 0) {
                const int j = __ffs(m) - 1; m &= m - 1; tot--;
                float4 t = __ldcs(&T4[(rowbase + j) * 32 + lane]);
                float4 f = __ldg(&nf4[(size_t)(jbase + j) * 32 + lane]);
                a0.x += f.x*t.x; a0.y += f.y*t.y; a0.z += f.z*t.z; a0.w += f.w*t.w;
            }
        }

        a0.x += a1.x + a2.x + a3.x;
        a0.y += a1.y + a2.y + a3.y;
        a0.z += a1.z + a2.z + a3.z;
        a0.w += a1.w + a2.w + a3.w;

        ((float4*)g_part)[((size_t)jb * NN + i) * 32 + lane] = a0;
    } else {
        // ---------------- gh GEMM: C[1024x384] = nf @ whh^T --------------
        const int g  = bx - 1024;           // 0..191
        const int mt = g & 31;              // 32 m-tiles of 32 rows
        const int nt = g >> 5;              // 6 n-tiles of 64 cols
        const int tx = tid & 15;            // 4-col group
        const int ty = tid >> 4;            // 2-row group

        const float4* A4 = (const float4*)nf;
        const float4* W4 = (const float4*)whh;
        float4*       C4 = (float4*)g_gh;

        const int mbase = mt * 32;
        const int nbase = nt * 64;

        float c00=0,c01=0,c02=0,c03=0, c10=0,c11=0,c12=0,c13=0;

        #pragma unroll
        for (int kb = 0; kb < 4; kb++) {
            {   // stage A: 256 f4, one per thread
                const int m = tid >> 3, kq = tid & 7;
                sA[m][kq] = A4[(size_t)(mbase + m) * 32 + kb * 8 + kq];
            }
            #pragma unroll
            for (int e = tid; e < 64 * 8; e += 256) {   // stage B: 512 f4
                const int n = e >> 3, kq = e & 7;
                sB[n][kq] = W4[(size_t)(nbase + n) * 32 + kb * 8 + kq];
            }
            __syncthreads();

            #pragma unroll
            for (int kq = 0; kq < 8; kq++) {
                const float4 a0 = sA[ty * 2 + 0][kq];
                const float4 a1 = sA[ty * 2 + 1][kq];
                const float4 b0 = sB[tx * 4 + 0][kq];
                const float4 b1 = sB[tx * 4 + 1][kq];
                const float4 b2 = sB[tx * 4 + 2][kq];
                const float4 b3 = sB[tx * 4 + 3][kq];
                c00 += a0.x*b0.x + a0.y*b0.y + a0.z*b0.z + a0.w*b0.w;
                c01 += a0.x*b1.x + a0.y*b1.y + a0.z*b1.z + a0.w*b1.w;
                c02 += a0.x*b2.x + a0.y*b2.y + a0.z*b2.z + a0.w*b2.w;
                c03 += a0.x*b3.x + a0.y*b3.y + a0.z*b3.z + a0.w*b3.w;
                c10 += a1.x*b0.x + a1.y*b0.y + a1.z*b0.z + a1.w*b0.w;
                c11 += a1.x*b1.x + a1.y*b1.y + a1.z*b1.z + a1.w*b1.w;
                c12 += a1.x*b2.x + a1.y*b2.y + a1.z*b2.z + a1.w*b2.w;
                c13 += a1.x*b3.x + a1.y*b3.y + a1.z*b3.z + a1.w*b3.w;
            }
            __syncthreads();
        }

        const int m0 = mbase + ty * 2;
        const int n4 = nt * 16 + tx;
        C4[(size_t)(m0 + 0) * 96 + n4] = make_float4(c00, c01, c02, c03);
        C4[(size_t)(m0 + 1) * 96 + n4] = make_float4(c10, c11, c12, c13);
    }
}

// ---------------------------------------------------------------------------
// Kernel B: gi GEMM  g_gi[1024x384] = sum(g_part) @ wih^T.
// Round-9 tiled gemm, z=0 path only. grid (16, 6).
// ---------------------------------------------------------------------------
__global__ __launch_bounds__(256) void gi_gemm_kernel(
    const float* __restrict__ wih)
{
    const int mt  = blockIdx.x;
    const int nt  = blockIdx.y;
    const int tid = threadIdx.x;
    const int tx  = tid & 15;
    const int ty  = tid >> 4;

    const float4* P4 = (const float4*)g_part;
    const float4* W4 = (const float4*)wih;
    float4*       C4 = (float4*)g_gi;

    __shared__ float4 sA[64][17];
    __shared__ float4 sB[64][17];

    const int mbase = mt * 64;
    const int nbase = nt * 64;

    float c00=0,c01=0,c02=0,c03=0, c10=0,c11=0,c12=0,c13=0;
    float c20=0,c21=0,c22=0,c23=0, c30=0,c31=0,c32=0,c33=0;

    #pragma unroll
    for (int kb = 0; kb < 2; kb++) {
        #pragma unroll
        for (int e = tid; e < 64 * 16; e += 256) {
            const int m = e >> 4, kq = e & 15;
            const size_t gidx = (size_t)(mbase + m) * 32 + kb * 16 + kq;
            float4 s = P4[gidx];
            #pragma unroll
            for (int p = 1; p < NJB; p++) {
                float4 v = P4[(size_t)p * (NN * 32) + gidx];
                s.x += v.x; s.y += v.y; s.z += v.z; s.w += v.w;
            }
            sA[m][kq] = s;
        }
        #pragma unroll
        for (int e = tid; e < 64 * 16; e += 256) {
            const int n = e >> 4, kq = e & 15;
            sB[n][kq] = W4[(size_t)(nbase + n) * 32 + kb * 16 + kq];
        }
        __syncthreads();

        #pragma unroll
        for (int kq = 0; kq < 16; kq++) {
            const float4 a0 = sA[ty * 4 + 0][kq];
            const float4 a1 = sA[ty * 4 + 1][kq];
            const float4 a2 = sA[ty * 4 + 2][kq];
            const float4 a3 = sA[ty * 4 + 3][kq];
            const float4 b0 = sB[tx * 4 + 0][kq];
            const float4 b1 = sB[tx * 4 + 1][kq];
            const float4 b2 = sB[tx * 4 + 2][kq];
            const float4 b3 = sB[tx * 4 + 3][kq];

            c00 += a0.x*b0.x + a0.y*b0.y + a0.z*b0.z + a0.w*b0.w;
            c01 += a0.x*b1.x + a0.y*b1.y + a0.z*b1.z + a0.w*b1.w;
            c02 += a0.x*b2.x + a0.y*b2.y + a0.z*b2.z + a0.w*b2.w;
            c03 += a0.x*b3.x + a0.y*b3.y + a0.z*b3.z + a0.w*b3.w;
            c10 += a1.x*b0.x + a1.y*b0.y + a1.z*b0.z + a1.w*b0.w;
            c11 += a1.x*b1.x + a1.y*b1.y + a1.z*b1.z + a1.w*b1.w;
            c12 += a1.x*b2.x + a1.y*b2.y + a1.z*b2.z + a1.w*b2.w;
            c13 += a1.x*b3.x + a1.y*b3.y + a1.z*b3.z + a1.w*b3.w;
            c20 += a2.x*b0.x + a2.y*b0.y + a2.z*b0.z + a2.w*b0.w;
            c21 += a2.x*b1.x + a2.y*b1.y + a2.z*b1.z + a2.w*b1.w;
            c22 += a2.x*b2.x + a2.y*b2.y + a2.z*b2.z + a2.w*b2.w;
            c23 += a2.x*b3.x + a2.y*b3.y + a2.z*b3.z + a2.w*b3.w;
            c30 += a3.x*b0.x + a3.y*b0.y + a3.z*b0.z + a3.w*b0.w;
            c31 += a3.x*b1.x + a3.y*b1.y + a3.z*b1.z + a3.w*b1.w;
            c32 += a3.x*b2.x + a3.y*b2.y + a3.z*b2.z + a3.w*b2.w;
            c33 += a3.x*b3.x + a3.y*b3.y + a3.z*b3.z + a3.w*b3.w;
        }
        __syncthreads();
    }

    const int m0 = mbase + ty * 4;
    const int n4 = nt * 16 + tx;
    C4[(size_t)(m0 + 0) * 96 + n4] = make_float4(c00, c01, c02, c03);
    C4[(size_t)(m0 + 1) * 96 + n4] = make_float4(c10, c11, c12, c13);
    C4[(size_t)(m0 + 2) * 96 + n4] = make_float4(c20, c21, c22, c23);
    C4[(size_t)(m0 + 3) * 96 + n4] = make_float4(c30, c31, c32, c33);
}

// ---------------------------------------------------------------------------
// Kernel C: fused GRU epilogue. One thread per (i,h).
// ---------------------------------------------------------------------------
__global__ __launch_bounds__(256) void gru_ep_kernel(
    const float* __restrict__ nf,
    const float* __restrict__ bih,
    const float* __restrict__ bhh,
    float*       __restrict__ out)
{
    const int idx = blockIdx.x * 256 + threadIdx.x;   // i*128 + h
    const int i = idx >> 7;
    const int h = idx & 127;
    const size_t base = (size_t)i * 384 + h;

    const float r = 1.f / (1.f + __expf(-(g_gi[base] + g_gh[base]
                                          + bih[h] + bhh[h])));
    const float z = 1.f / (1.f + __expf(-(g_gi[base + 128] + g_gh[base + 128]
                                          + bih[h + 128] + bhh[h + 128])));
    const float n = tanhf(g_gi[base + 256] + bih[h + 256]
                          + r * (g_gh[base + 256] + bhh[h + 256]));
    out[idx] = (1.f - z) * n + z * nf[idx];
}

extern "C" void kernel_launch(void* const* d_in, const int* in_sizes, int n_in,
                              void* d_out, int out_size)
{
    const float* nf  = (const float*)d_in[0];
    const int*   adj = (const int*)  d_in[1];
    const float* T   = (const float*)d_in[2];
    const float* wih = (const float*)d_in[3];
    const float* whh = (const float*)d_in[4];
    const float* bih = (const float*)d_in[5];
    const float* bhh = (const float*)d_in[6];
    float* out = (float*)d_out;

    fused_agg_gh_kernel<<<1024 + 192, 256>>>(nf, adj, T, whh);
    gi_gemm_kernel<<<dim3(16, 6), 256>>>(wih);
    gru_ep_kernel<<<(NN * HH) / 256, 256>>>(nf, bih, bhh, out);
}

// round 11
// speedup vs baseline: 1.0987x; 1.0987x over previous
#include <cuda_runtime.h>

#define NN 1024
#define HH 128
#define NJB 8           // j-blocks of 128
#define NGH 192         // gh-gemm CTAs, scheduled FIRST

// Device-global scratch (no allocation allowed)
__device__ float g_part[NJB * NN * HH];   // per-jblock partial aggregates
__device__ float g_gi[NN * 3 * HH];       // gi = agg @ w_ih^T   [1024][384]
__device__ float g_gh[NN * 3 * HH];       // gh = nf  @ w_hh^T   [1024][384]

// ---------------------------------------------------------------------------
// Kernel A: fused [gh-GEMM || agg], gemm blocks first so they land in wave 1
// alongside agg and finish under agg's DRAM-bound window.
// blocks [0,192):    gh = nf @ whh^T, 32x64 tile, 2x4 microtile (low regs)
// blocks [192,1216): barrier-free partial aggregation (round-9 code, at its
//                    measured ~4.6 TB/s gated-scatter DRAM floor)
// ---------------------------------------------------------------------------
__global__ __launch_bounds__(256) void fused_gh_agg_kernel(
    const float* __restrict__ nf,
    const int*   __restrict__ adj,
    const float* __restrict__ T,
    const float* __restrict__ whh)
{
    __shared__ float4 sA[32][9];   // gemm branch only (~14 KB total)
    __shared__ float4 sB[64][9];

    const int bx  = blockIdx.x;
    const int tid = threadIdx.x;

    if (bx < NGH) {
        // ---------------- gh GEMM: C[1024x384] = nf @ whh^T --------------
        const int mt = bx & 31;             // 32 m-tiles of 32 rows
        const int nt = bx >> 5;             // 6 n-tiles of 64 cols
        const int tx = tid & 15;            // 4-col group
        const int ty = tid >> 4;            // 2-row group

        const float4* A4 = (const float4*)nf;
        const float4* W4 = (const float4*)whh;
        float4*       C4 = (float4*)g_gh;

        const int mbase = mt * 32;
        const int nbase = nt * 64;

        float c00=0,c01=0,c02=0,c03=0, c10=0,c11=0,c12=0,c13=0;

        #pragma unroll
        for (int kb = 0; kb < 4; kb++) {
            {   // stage A: 256 f4, one per thread
                const int m = tid >> 3, kq = tid & 7;
                sA[m][kq] = A4[(size_t)(mbase + m) * 32 + kb * 8 + kq];
            }
            #pragma unroll
            for (int e = tid; e < 64 * 8; e += 256) {   // stage B: 512 f4
                const int n = e >> 3, kq = e & 7;
                sB[n][kq] = W4[(size_t)(nbase + n) * 32 + kb * 8 + kq];
            }
            __syncthreads();

            #pragma unroll
            for (int kq = 0; kq < 8; kq++) {
                const float4 a0 = sA[ty * 2 + 0][kq];
                const float4 a1 = sA[ty * 2 + 1][kq];
                const float4 b0 = sB[tx * 4 + 0][kq];
                const float4 b1 = sB[tx * 4 + 1][kq];
                const float4 b2 = sB[tx * 4 + 2][kq];
                const float4 b3 = sB[tx * 4 + 3][kq];
                c00 += a0.x*b0.x + a0.y*b0.y + a0.z*b0.z + a0.w*b0.w;
                c01 += a0.x*b1.x + a0.y*b1.y + a0.z*b1.z + a0.w*b1.w;
                c02 += a0.x*b2.x + a0.y*b2.y + a0.z*b2.z + a0.w*b2.w;
                c03 += a0.x*b3.x + a0.y*b3.y + a0.z*b3.z + a0.w*b3.w;
                c10 += a1.x*b0.x + a1.y*b0.y + a1.z*b0.z + a1.w*b0.w;
                c11 += a1.x*b1.x + a1.y*b1.y + a1.z*b1.z + a1.w*b1.w;
                c12 += a1.x*b2.x + a1.y*b2.y + a1.z*b2.z + a1.w*b2.w;
                c13 += a1.x*b3.x + a1.y*b3.y + a1.z*b3.z + a1.w*b3.w;
            }
            __syncthreads();
        }

        const int m0 = mbase + ty * 2;
        const int n4 = nt * 16 + tx;
        C4[(size_t)(m0 + 0) * 96 + n4] = make_float4(c00, c01, c02, c03);
        C4[(size_t)(m0 + 1) * 96 + n4] = make_float4(c10, c11, c12, c13);
    } else {
        // ---------------- aggregation (unchanged round 9) ----------------
        const int ab   = bx - NGH;
        const int ib   = ab & 127;
        const int jb   = ab >> 7;
        const int lane = tid & 31;
        const int w    = tid >> 5;
        const int i    = ib * 8 + w;

        const float4* nf4 = (const float4*)nf;
        const float4* T4  = (const float4*)T;

        float4 a0 = make_float4(0.f,0.f,0.f,0.f);
        float4 a1 = make_float4(0.f,0.f,0.f,0.f);
        float4 a2 = make_float4(0.f,0.f,0.f,0.f);
        float4 a3 = make_float4(0.f,0.f,0.f,0.f);

        const int* adjrow = adj + (size_t)i * NN + jb * 128;

        #pragma unroll 1
        for (int c = 0; c < 4; c++) {
            const int av = __ldg(&adjrow[c * 32 + lane]);
            unsigned m = __ballot_sync(0xffffffffu, av != 0);
            int tot = __popc(m);

            const int    jbase   = jb * 128 + c * 32;
            const size_t rowbase = (size_t)i * NN + jbase;

            while (tot >= 4) {
                const int j0 = __ffs(m) - 1; m &= m - 1;
                const int j1 = __ffs(m) - 1; m &= m - 1;
                const int j2 = __ffs(m) - 1; m &= m - 1;
                const int j3 = __ffs(m) - 1; m &= m - 1;
                tot -= 4;
                float4 t0 = __ldcs(&T4[(rowbase + j0) * 32 + lane]);
                float4 t1 = __ldcs(&T4[(rowbase + j1) * 32 + lane]);
                float4 t2 = __ldcs(&T4[(rowbase + j2) * 32 + lane]);
                float4 t3 = __ldcs(&T4[(rowbase + j3) * 32 + lane]);
                float4 f0 = __ldg(&nf4[(size_t)(jbase + j0) * 32 + lane]);
                float4 f1 = __ldg(&nf4[(size_t)(jbase + j1) * 32 + lane]);
                float4 f2 = __ldg(&nf4[(size_t)(jbase + j2) * 32 + lane]);
                float4 f3 = __ldg(&nf4[(size_t)(jbase + j3) * 32 + lane]);
                a0.x += f0.x*t0.x; a0.y += f0.y*t0.y; a0.z += f0.z*t0.z; a0.w += f0.w*t0.w;
                a1.x += f1.x*t1.x; a1.y += f1.y*t1.y; a1.z += f1.z*t1.z; a1.w += f1.w*t1.w;
                a2.x += f2.x*t2.x; a2.y += f2.y*t2.y; a2.z += f2.z*t2.z; a2.w += f2.w*t2.w;
                a3.x += f3.x*t3.x; a3.y += f3.y*t3.y; a3.z += f3.z*t3.z; a3.w += f3.w*t3.w;
            }
            while (tot > 0) {
                const int j = __ffs(m) - 1; m &= m - 1; tot--;
                float4 t = __ldcs(&T4[(rowbase + j) * 32 + lane]);
                float4 f = __ldg(&nf4[(size_t)(jbase + j) * 32 + lane]);
                a0.x += f.x*t.x; a0.y += f.y*t.y; a0.z += f.z*t.z; a0.w += f.w*t.w;
            }
        }

        a0.x += a1.x + a2.x + a3.x;
        a0.y += a1.y + a2.y + a3.y;
        a0.z += a1.z + a2.z + a3.z;
        a0.w += a1.w + a2.w + a3.w;

        ((float4*)g_part)[((size_t)jb * NN + i) * 32 + lane] = a0;
    }
}

// ---------------------------------------------------------------------------
// Kernel B: gi GEMM  g_gi[1024x384] = sum(g_part) @ wih^T. grid (16, 6).
// ---------------------------------------------------------------------------
__global__ __launch_bounds__(256) void gi_gemm_kernel(
    const float* __restrict__ wih)
{
    const int mt  = blockIdx.x;
    const int nt  = blockIdx.y;
    const int tid = threadIdx.x;
    const int tx  = tid & 15;
    const int ty  = tid >> 4;

    const float4* P4 = (const float4*)g_part;
    const float4* W4 = (const float4*)wih;
    float4*       C4 = (float4*)g_gi;

    __shared__ float4 sA[64][17];
    __shared__ float4 sB[64][17];

    const int mbase = mt * 64;
    const int nbase = nt * 64;

    float c00=0,c01=0,c02=0,c03=0, c10=0,c11=0,c12=0,c13=0;
    float c20=0,c21=0,c22=0,c23=0, c30=0,c31=0,c32=0,c33=0;

    #pragma unroll
    for (int kb = 0; kb < 2; kb++) {
        #pragma unroll
        for (int e = tid; e < 64 * 16; e += 256) {
            const int m = e >> 4, kq = e & 15;
            const size_t gidx = (size_t)(mbase + m) * 32 + kb * 16 + kq;
            float4 s = P4[gidx];
            #pragma unroll
            for (int p = 1; p < NJB; p++) {
                float4 v = P4[(size_t)p * (NN * 32) + gidx];
                s.x += v.x; s.y += v.y; s.z += v.z; s.w += v.w;
            }
            sA[m][kq] = s;
        }
        #pragma unroll
        for (int e = tid; e < 64 * 16; e += 256) {
            const int n = e >> 4, kq = e & 15;
            sB[n][kq] = W4[(size_t)(nbase + n) * 32 + kb * 16 + kq];
        }
        __syncthreads();

        #pragma unroll
        for (int kq = 0; kq < 16; kq++) {
            const float4 a0 = sA[ty * 4 + 0][kq];
            const float4 a1 = sA[ty * 4 + 1][kq];
            const float4 a2 = sA[ty * 4 + 2][kq];
            const float4 a3 = sA[ty * 4 + 3][kq];
            const float4 b0 = sB[tx * 4 + 0][kq];
            const float4 b1 = sB[tx * 4 + 1][kq];
            const float4 b2 = sB[tx * 4 + 2][kq];
            const float4 b3 = sB[tx * 4 + 3][kq];

            c00 += a0.x*b0.x + a0.y*b0.y + a0.z*b0.z + a0.w*b0.w;
            c01 += a0.x*b1.x + a0.y*b1.y + a0.z*b1.z + a0.w*b1.w;
            c02 += a0.x*b2.x + a0.y*b2.y + a0.z*b2.z + a0.w*b2.w;
            c03 += a0.x*b3.x + a0.y*b3.y + a0.z*b3.z + a0.w*b3.w;
            c10 += a1.x*b0.x + a1.y*b0.y + a1.z*b0.z + a1.w*b0.w;
            c11 += a1.x*b1.x + a1.y*b1.y + a1.z*b1.z + a1.w*b1.w;
            c12 += a1.x*b2.x + a1.y*b2.y + a1.z*b2.z + a1.w*b2.w;
            c13 += a1.x*b3.x + a1.y*b3.y + a1.z*b3.z + a1.w*b3.w;
            c20 += a2.x*b0.x + a2.y*b0.y + a2.z*b0.z + a2.w*b0.w;
            c21 += a2.x*b1.x + a2.y*b1.y + a2.z*b1.z + a2.w*b1.w;
            c22 += a2.x*b2.x + a2.y*b2.y + a2.z*b2.z + a2.w*b2.w;
            c23 += a2.x*b3.x + a2.y*b3.y + a2.z*b3.z + a2.w*b3.w;
            c30 += a3.x*b0.x + a3.y*b0.y + a3.z*b0.z + a3.w*b0.w;
            c31 += a3.x*b1.x + a3.y*b1.y + a3.z*b1.z + a3.w*b1.w;
            c32 += a3.x*b2.x + a3.y*b2.y + a3.z*b2.z + a3.w*b2.w;
            c33 += a3.x*b3.x + a3.y*b3.y + a3.z*b3.z + a3.w*b3.w;
        }
        __syncthreads();
    }

    const int m0 = mbase + ty * 4;
    const int n4 = nt * 16 + tx;
    C4[(size_t)(m0 + 0) * 96 + n4] = make_float4(c00, c01, c02, c03);
    C4[(size_t)(m0 + 1) * 96 + n4] = make_float4(c10, c11, c12, c13);
    C4[(size_t)(m0 + 2) * 96 + n4] = make_float4(c20, c21, c22, c23);
    C4[(size_t)(m0 + 3) * 96 + n4] = make_float4(c30, c31, c32, c33);
}

// ---------------------------------------------------------------------------
// Kernel C: fused GRU epilogue. One thread per (i,h).
// ---------------------------------------------------------------------------
__global__ __launch_bounds__(256) void gru_ep_kernel(
    const float* __restrict__ nf,
    const float* __restrict__ bih,
    const float* __restrict__ bhh,
    float*       __restrict__ out)
{
    const int idx = blockIdx.x * 256 + threadIdx.x;   // i*128 + h
    const int i = idx >> 7;
    const int h = idx & 127;
    const size_t base = (size_t)i * 384 + h;

    const float r = 1.f / (1.f + __expf(-(g_gi[base] + g_gh[base]
                                          + bih[h] + bhh[h])));
    const float z = 1.f / (1.f + __expf(-(g_gi[base + 128] + g_gh[base + 128]
                                          + bih[h + 128] + bhh[h + 128])));
    const float n = tanhf(g_gi[base + 256] + bih[h + 256]
                          + r * (g_gh[base + 256] + bhh[h + 256]));
    out[idx] = (1.f - z) * n + z * nf[idx];
}

extern "C" void kernel_launch(void* const* d_in, const int* in_sizes, int n_in,
                              void* d_out, int out_size)
{
    const float* nf  = (const float*)d_in[0];
    const int*   adj = (const int*)  d_in[1];
    const float* T   = (const float*)d_in[2];
    const float* wih = (const float*)d_in[3];
    const float* whh = (const float*)d_in[4];
    const float* bih = (const float*)d_in[5];
    const float* bhh = (const float*)d_in[6];
    float* out = (float*)d_out;

    fused_gh_agg_kernel<<<NGH + NN, 256>>>(nf, adj, T, whh);
    gi_gemm_kernel<<<dim3(16, 6), 256>>>(wih);
    gru_ep_kernel<<<(NN * HH) / 256, 256>>>(nf, bih, bhh, out);
}